// round 10
// baseline (speedup 1.0000x reference)
#include <cuda_runtime.h>
#include <cuda_bf16.h>
#include <cstdint>

#define B_  2
#define S_  2048
#define D_  1024
#define H_  16
#define HD_ 64
#define M_  (B_*S_)   // 4096 rows
#define NW  (D_*D_)

// bf16 split scratch
__device__ __nv_bfloat16 g_xh[M_*D_];
__device__ __nv_bfloat16 g_xl[M_*D_];
__device__ __nv_bfloat16 g_wh[4][D_*D_];
__device__ __nv_bfloat16 g_wl[4][D_*D_];
// attention operands (head-major)
__device__ __nv_bfloat16 g_qh2[M_*D_];
__device__ __nv_bfloat16 g_ql2[M_*D_];
__device__ __nv_bfloat16 g_kh2[M_*D_];
__device__ __nv_bfloat16 g_kl2[M_*D_];
__device__ __nv_bfloat16 g_vth[M_*D_];
__device__ __nv_bfloat16 g_vtl[M_*D_];

// ---------------------------------------------------------------------------
// base-ISA PTX helpers (compute_103 generic: no tcgen05 available)
// ---------------------------------------------------------------------------
__device__ __forceinline__ uint32_t smem_to_u32(const void* p) {
    uint32_t a;
    asm("{ .reg .u64 tmp; cvta.to.shared.u64 tmp, %1; cvt.u32.u64 %0, tmp; }"
        : "=r"(a) : "l"(p));
    return a;
}
#define CP_ASYNC16(dst, src) \
    asm volatile("cp.async.cg.shared.global [%0], [%1], 16;" :: "r"(dst), "l"(src))
#define CP_COMMIT() asm volatile("cp.async.commit_group;" ::: "memory")
#define CP_WAIT0()  asm volatile("cp.async.wait_group 0;" ::: "memory")
#define CP_WAIT1()  asm volatile("cp.async.wait_group 1;" ::: "memory")

__device__ __forceinline__ void ldmx4(uint32_t* r, uint32_t addr) {
    asm volatile("ldmatrix.sync.aligned.m8n8.x4.shared.b16 {%0,%1,%2,%3}, [%4];"
        : "=r"(r[0]), "=r"(r[1]), "=r"(r[2]), "=r"(r[3]) : "r"(addr));
}
__device__ __forceinline__ void mma16816(float* c, const uint32_t* a, const uint32_t* b) {
    asm volatile("mma.sync.aligned.m16n8k16.row.col.f32.bf16.bf16.f32 "
        "{%0,%1,%2,%3}, {%4,%5,%6,%7}, {%8,%9}, {%0,%1,%2,%3};"
        : "+f"(c[0]), "+f"(c[1]), "+f"(c[2]), "+f"(c[3])
        : "r"(a[0]), "r"(a[1]), "r"(a[2]), "r"(a[3]), "r"(b[0]), "r"(b[1]));
}
__device__ __forceinline__ uint32_t pack_bf2(float a, float b) {   // low=a, high=b
    uint32_t r;
    asm("cvt.rn.bf16x2.f32 %0, %1, %2;" : "=r"(r) : "f"(b), "f"(a));
    return r;
}
__device__ __forceinline__ float bf_hi(float x) {
    return __bfloat162float(__float2bfloat16_rn(x));
}
__device__ __forceinline__ float bf_res(float x) { return x - bf_hi(x); }

// ---------------------------------------------------------------------------
// split_all: one launch splits x (1M float4) + 4 weights (256K float4 each)
// ---------------------------------------------------------------------------
#define XF4 (M_*D_/4)      // 1048576
#define WF4 (NW/4)         // 262144
__global__ __launch_bounds__(256) void split_all(
    const float* __restrict__ x,  const float* __restrict__ wq,
    const float* __restrict__ wk, const float* __restrict__ wv,
    const float* __restrict__ wo,
    __nv_bfloat16* __restrict__ xh, __nv_bfloat16* __restrict__ xl,
    __nv_bfloat16* __restrict__ wh, __nv_bfloat16* __restrict__ wl)
{
    int i = blockIdx.x * blockDim.x + threadIdx.x;
    const float* src;
    uint32_t *hi, *lo;
    int off;
    if (i < XF4) {
        src = x; hi = (uint32_t*)xh; lo = (uint32_t*)xl; off = i;
    } else {
        int j = i - XF4;
        int w = j >> 18;            // WF4 = 2^18
        off = j & (WF4 - 1);
        src = (w == 0) ? wq : (w == 1) ? wk : (w == 2) ? wv : wo;
        hi  = (uint32_t*)(wh + (size_t)w * NW);
        lo  = (uint32_t*)(wl + (size_t)w * NW);
    }
    float4 v = ((const float4*)src)[off];
    float hx = bf_hi(v.x), hy = bf_hi(v.y), hz = bf_hi(v.z), hw = bf_hi(v.w);
    hi[off*2]   = pack_bf2(hx, hy);
    hi[off*2+1] = pack_bf2(hz, hw);
    lo[off*2]   = pack_bf2(v.x - hx, v.y - hy);
    lo[off*2+1] = pack_bf2(v.z - hz, v.w - hw);
}

// ---------------------------------------------------------------------------
// HMMA GEMM core (validated): C = Ah*Bh^T + Ah*Bl^T + Al*Bh^T into c[2][8][4]
// ---------------------------------------------------------------------------
#define BK    32
#define ASTR  40
#define BUFB  (128*ASTR*2)
#define STAGEB (4*BUFB)
#define GSMEM (2*STAGEB)

__device__ __forceinline__ void stage_load(
    uint32_t sbase,
    const __nv_bfloat16* __restrict__ Ah, const __nv_bfloat16* __restrict__ Al,
    const __nv_bfloat16* __restrict__ Bh, const __nv_bfloat16* __restrict__ Bl,
    int m0, int n0, int kc, int tid)
{
    int r  = tid >> 1;
    int ch = (tid & 1) * 16;
    uint32_t so = (uint32_t)(r * (ASTR*2) + ch * 2);
    size_t ga = (size_t)(m0 + r) * D_ + kc + ch;
    size_t gb = (size_t)(n0 + r) * D_ + kc + ch;
    CP_ASYNC16(sbase + 0*BUFB + so,      Ah + ga);
    CP_ASYNC16(sbase + 0*BUFB + so + 16, Ah + ga + 8);
    CP_ASYNC16(sbase + 1*BUFB + so,      Al + ga);
    CP_ASYNC16(sbase + 1*BUFB + so + 16, Al + ga + 8);
    CP_ASYNC16(sbase + 2*BUFB + so,      Bh + gb);
    CP_ASYNC16(sbase + 2*BUFB + so + 16, Bh + gb + 8);
    CP_ASYNC16(sbase + 3*BUFB + so,      Bl + gb);
    CP_ASYNC16(sbase + 3*BUFB + so + 16, Bl + gb + 8);
}

#define GEMM_MAINLOOP(AhP, AlP, BhP, BlP)                                        \
    int wm = (wid >> 1) * 32;                                                    \
    int wn = (wid & 1) * 64;                                                     \
    int qq = lane >> 3, lr = lane & 7;                                           \
    uint32_t a_row = (uint32_t)((qq & 1) * 8 + lr);                              \
    uint32_t a_kc  = (uint32_t)((qq >> 1) * 8);                                  \
    uint32_t b_row = (uint32_t)((qq >> 1) * 8 + lr);                             \
    uint32_t b_kc  = (uint32_t)((qq & 1) * 8);                                   \
    float c[2][8][4];                                                            \
    _Pragma("unroll")                                                            \
    for (int mt = 0; mt < 2; mt++)                                               \
        _Pragma("unroll")                                                        \
        for (int nt = 0; nt < 8; nt++)                                           \
            _Pragma("unroll")                                                    \
            for (int i = 0; i < 4; i++) c[mt][nt][i] = 0.f;                      \
    stage_load(sb,          AhP, AlP, BhP, BlP, m0, n0, 0,  tid); CP_COMMIT();   \
    stage_load(sb + STAGEB, AhP, AlP, BhP, BlP, m0, n0, BK, tid); CP_COMMIT();   \
    const int NCH = D_ / BK;                                                     \
    for (int cc = 0; cc < NCH; cc++) {                                           \
        uint32_t stage = sb + (uint32_t)(cc & 1) * STAGEB;                       \
        CP_WAIT1();                                                              \
        __syncthreads();                                                         \
        uint32_t sAh = stage + 0*BUFB, sAl = stage + 1*BUFB;                     \
        uint32_t sBh = stage + 2*BUFB, sBl = stage + 3*BUFB;                     \
        _Pragma("unroll")                                                        \
        for (int ks = 0; ks < 2; ks++) {                                         \
            uint32_t koff = (uint32_t)(ks * 16) * 2;                             \
            uint32_t ah[2][4], al[2][4], bfr[8][2];                              \
            _Pragma("unroll")                                                    \
            for (int mt = 0; mt < 2; mt++)                                       \
                ldmx4(ah[mt], sAh + ((uint32_t)(wm + mt*16) + a_row) * (ASTR*2) + koff + a_kc*2); \
            _Pragma("unroll")                                                    \
            for (int mt = 0; mt < 2; mt++)                                       \
                ldmx4(al[mt], sAl + ((uint32_t)(wm + mt*16) + a_row) * (ASTR*2) + koff + a_kc*2); \
            _Pragma("unroll")                                                    \
            for (int np = 0; np < 4; np++) {                                     \
                uint32_t r4[4];                                                  \
                ldmx4(r4, sBh + ((uint32_t)(wn + np*16) + b_row) * (ASTR*2) + koff + b_kc*2); \
                bfr[2*np][0] = r4[0]; bfr[2*np][1] = r4[1];                      \
                bfr[2*np+1][0] = r4[2]; bfr[2*np+1][1] = r4[3];                  \
            }                                                                    \
            _Pragma("unroll")                                                    \
            for (int mt = 0; mt < 2; mt++)                                       \
                _Pragma("unroll")                                                \
                for (int nt = 0; nt < 8; nt++)                                   \
                    mma16816(c[mt][nt], ah[mt], bfr[nt]);                        \
            _Pragma("unroll")                                                    \
            for (int mt = 0; mt < 2; mt++)                                       \
                _Pragma("unroll")                                                \
                for (int nt = 0; nt < 8; nt++)                                   \
                    mma16816(c[mt][nt], al[mt], bfr[nt]);                        \
            _Pragma("unroll")                                                    \
            for (int np = 0; np < 4; np++) {                                     \
                uint32_t r4[4];                                                  \
                ldmx4(r4, sBl + ((uint32_t)(wn + np*16) + b_row) * (ASTR*2) + koff + b_kc*2); \
                bfr[2*np][0] = r4[0]; bfr[2*np][1] = r4[1];                      \
                bfr[2*np+1][0] = r4[2]; bfr[2*np+1][1] = r4[3];                  \
            }                                                                    \
            _Pragma("unroll")                                                    \
            for (int mt = 0; mt < 2; mt++)                                       \
                _Pragma("unroll")                                                \
                for (int nt = 0; nt < 8; nt++)                                   \
                    mma16816(c[mt][nt], ah[mt], bfr[nt]);                        \
        }                                                                        \
        __syncthreads();                                                         \
        if (cc + 2 < NCH)                                                        \
            stage_load(stage, AhP, AlP, BhP, BlP, m0, n0, (cc + 2) * BK, tid);   \
        CP_COMMIT();                                                             \
    }

// ---------------------------------------------------------------------------
// fused QKV projection: z=0 -> Q split head-major (scale 1/8)
//                       z=1 -> K split head-major
//                       z=2 -> V split TRANSPOSED [b,h,64,s] via smem
// ---------------------------------------------------------------------------
#define TP_STR 129   // fp32 transpose buffer stride

__global__ __launch_bounds__(256) void gemm_qkv(
    const __nv_bfloat16* __restrict__ Xh, const __nv_bfloat16* __restrict__ Xl,
    const __nv_bfloat16* __restrict__ Wh, const __nv_bfloat16* __restrict__ Wl,
    __nv_bfloat16* __restrict__ Qh, __nv_bfloat16* __restrict__ Ql,
    __nv_bfloat16* __restrict__ Kh, __nv_bfloat16* __restrict__ Kl,
    __nv_bfloat16* __restrict__ VTh, __nv_bfloat16* __restrict__ VTl)
{
    extern __shared__ char smem[];
    uint32_t sb = smem_to_u32(smem);
    int tid = threadIdx.x, wid = tid >> 5, lane = tid & 31;
    int n0 = blockIdx.x * 128;
    int m0 = blockIdx.y * 128;
    int z  = blockIdx.z;
    const __nv_bfloat16* Bh = Wh + (size_t)z * NW;
    const __nv_bfloat16* Bl = Wl + (size_t)z * NW;

    GEMM_MAINLOOP(Xh, Xl, Bh, Bl)

    int crow = lane >> 2, ccol = (lane & 3) * 2;
    if (z == 2) {
        // transpose through smem: T[n][m], then write split bf16 [b,h,64,s]
        float* T = (float*)smem;
        #pragma unroll
        for (int mt = 0; mt < 2; mt++)
            #pragma unroll
            for (int nt = 0; nt < 8; nt++) {
                int mm = wm + mt*16 + crow;
                int nn = wn + nt*8 + ccol;
                T[(nn  )*TP_STR + mm    ] = c[mt][nt][0];
                T[(nn+1)*TP_STR + mm    ] = c[mt][nt][1];
                T[(nn  )*TP_STR + mm + 8] = c[mt][nt][2];
                T[(nn+1)*TP_STR + mm + 8] = c[mt][nt][3];
            }
        __syncthreads();
        int n  = tid >> 1;               // 0..127 (d within the CTA's 2 heads)
        int ms = (tid & 1) * 64;         // s segment
        int b  = m0 >> 11;
        int sl = (m0 & (S_-1)) + ms;
        int h  = (n0 >> 6) + (n >> 6);
        int d  = n & 63;
        size_t ob = ((((size_t)(b*H_ + h)) * 64 + d) * S_ + sl) >> 1;
        uint32_t* OH = (uint32_t*)VTh;
        uint32_t* OL = (uint32_t*)VTl;
        #pragma unroll
        for (int j = 0; j < 32; j++) {
            float x0 = T[n*TP_STR + ms + 2*j];
            float x1 = T[n*TP_STR + ms + 2*j + 1];
            float h0 = bf_hi(x0), h1 = bf_hi(x1);
            OH[ob + j] = pack_bf2(h0, h1);
            OL[ob + j] = pack_bf2(x0 - h0, x1 - h1);
        }
    } else {
        float scale = (z == 0) ? 0.125f : 1.0f;
        uint32_t* Yh = (uint32_t*)((z == 0) ? Qh : Kh);
        uint32_t* Yl = (uint32_t*)((z == 0) ? Ql : Kl);
        #pragma unroll
        for (int mt = 0; mt < 2; mt++)
            #pragma unroll
            for (int nt = 0; nt < 8; nt++) {
                int m = m0 + wm + mt*16 + crow;
                int n = n0 + wn + nt*8 + ccol;
                int b = m >> 11, s = m & (S_-1);
                int h = n >> 6,  d = n & 63;
                size_t i0 = (((size_t)(b*H_ + h) * S_ + s) * 64 + d) >> 1;
                size_t i1 = i0 + (8 * 64 >> 1);
                float x0 = c[mt][nt][0]*scale, x1 = c[mt][nt][1]*scale;
                float x2 = c[mt][nt][2]*scale, x3 = c[mt][nt][3]*scale;
                float h0 = bf_hi(x0), h1 = bf_hi(x1), h2 = bf_hi(x2), h3 = bf_hi(x3);
                Yh[i0] = pack_bf2(h0, h1);
                Yl[i0] = pack_bf2(x0 - h0, x1 - h1);
                Yh[i1] = pack_bf2(h2, h3);
                Yl[i1] = pack_bf2(x2 - h2, x3 - h3);
            }
    }
}

// ---------------------------------------------------------------------------
// output projection: A = ctx split, + bias, fp32 out
// ---------------------------------------------------------------------------
__global__ __launch_bounds__(256) void gemm_out(
    const __nv_bfloat16* __restrict__ Ch, const __nv_bfloat16* __restrict__ Cl,
    const __nv_bfloat16* __restrict__ Bh, const __nv_bfloat16* __restrict__ Bl,
    const float* __restrict__ bias, float* __restrict__ Y)
{
    extern __shared__ char smem[];
    uint32_t sb = smem_to_u32(smem);
    int tid = threadIdx.x, wid = tid >> 5, lane = tid & 31;
    int n0 = blockIdx.x * 128;
    int m0 = blockIdx.y * 128;

    GEMM_MAINLOOP(Ch, Cl, Bh, Bl)

    int crow = lane >> 2, ccol = (lane & 3) * 2;
    #pragma unroll
    for (int mt = 0; mt < 2; mt++)
        #pragma unroll
        for (int nt = 0; nt < 8; nt++) {
            int m = m0 + wm + mt*16 + crow;
            int n = n0 + wn + nt*8 + ccol;
            float b0 = bias[n], b1 = bias[n+1];
            *(float2*)(Y + (size_t)m * D_ + n)     = make_float2(c[mt][nt][0]+b0, c[mt][nt][1]+b1);
            *(float2*)(Y + (size_t)(m+8) * D_ + n) = make_float2(c[mt][nt][2]+b0, c[mt][nt][3]+b1);
        }
}

// ---------------------------------------------------------------------------
// HMMA flash attention (validated core, unchanged)
// ---------------------------------------------------------------------------
#define TSTR  72
#define TROWB (TSTR*2)
#define TILEB (64*TROWB)
#define ABUF  (4*TILEB)
#define ATT_SMEM (2*ABUF)
#define QHB   (128*TROWB)

__device__ __forceinline__ void load_kv(
    uint32_t dst,
    const __nv_bfloat16* __restrict__ Kh, const __nv_bfloat16* __restrict__ Kl,
    const __nv_bfloat16* __restrict__ VTh, const __nv_bfloat16* __restrict__ VTl,
    size_t qko, size_t vto, int kt, int tid)
{
    int r = tid >> 2, seg = (tid & 3) * 16;
    uint32_t off = (uint32_t)(r * TROWB + seg * 2);
    const __nv_bfloat16* kh = Kh  + qko + (size_t)(kt*64 + r)*64 + seg;
    const __nv_bfloat16* kl = Kl  + qko + (size_t)(kt*64 + r)*64 + seg;
    const __nv_bfloat16* vh = VTh + vto + (size_t)r*S_ + kt*64 + seg;
    const __nv_bfloat16* vl = VTl + vto + (size_t)r*S_ + kt*64 + seg;
    CP_ASYNC16(dst + 0*TILEB + off,      kh);  CP_ASYNC16(dst + 0*TILEB + off + 16, kh + 8);
    CP_ASYNC16(dst + 1*TILEB + off,      kl);  CP_ASYNC16(dst + 1*TILEB + off + 16, kl + 8);
    CP_ASYNC16(dst + 2*TILEB + off,      vh);  CP_ASYNC16(dst + 2*TILEB + off + 16, vh + 8);
    CP_ASYNC16(dst + 3*TILEB + off,      vl);  CP_ASYNC16(dst + 3*TILEB + off + 16, vl + 8);
}

__global__ __launch_bounds__(256,1) void attn_hmma(
    const __nv_bfloat16* __restrict__ Qh, const __nv_bfloat16* __restrict__ Ql,
    const __nv_bfloat16* __restrict__ Kh, const __nv_bfloat16* __restrict__ Kl,
    const __nv_bfloat16* __restrict__ VTh, const __nv_bfloat16* __restrict__ VTl,
    __nv_bfloat16* __restrict__ Oh, __nv_bfloat16* __restrict__ Ol)
{
    extern __shared__ char smem[];
    uint32_t sb = smem_to_u32(smem);
    int tid = threadIdx.x, wid = tid >> 5, lane = tid & 31;
    int qt = (int)(gridDim.x - 1u - blockIdx.x);
    int h  = blockIdx.y, b = blockIdx.z;
    int bh = b*H_ + h;
    int qbase = qt * 128;
    size_t qko = (size_t)bh * S_ * 64;
    size_t vto = (size_t)bh * 64 * S_;

    int qq = lane >> 3, lr = lane & 7;
    uint32_t a_row = (uint32_t)((qq & 1) * 8 + lr);
    uint32_t a_kc  = (uint32_t)((qq >> 1) * 8);
    uint32_t b_row = (uint32_t)((qq >> 1) * 8 + lr);
    uint32_t b_kc  = (uint32_t)((qq & 1) * 8);

    {
        int r = tid >> 1, dseg = (tid & 1) * 32;
        const __nv_bfloat16* qh = Qh + qko + (size_t)(qbase + r)*64 + dseg;
        const __nv_bfloat16* ql = Ql + qko + (size_t)(qbase + r)*64 + dseg;
        uint32_t dq = sb + ABUF + (uint32_t)(r * TROWB + dseg * 2);
        #pragma unroll
        for (int i = 0; i < 4; i++) {
            CP_ASYNC16(dq + i*16,       qh + i*8);
            CP_ASYNC16(dq + QHB + i*16, ql + i*8);
        }
        CP_COMMIT();
    }
    load_kv(sb, Kh, Kl, VTh, VTl, qko, vto, 0, tid);
    CP_COMMIT();

    uint32_t qfh[4][4], qfl[4][4];
    CP_WAIT1();
    __syncthreads();
    {
        uint32_t qb = sb + ABUF + ((uint32_t)(wid*16) + a_row) * TROWB + a_kc*2;
        #pragma unroll
        for (int kc = 0; kc < 4; kc++) {
            ldmx4(qfh[kc], qb + kc*32);
            ldmx4(qfl[kc], qb + QHB + kc*32);
        }
    }
    __syncthreads();
    int ntiles = 2*qt + 2;
    load_kv(sb + ABUF, Kh, Kl, VTh, VTl, qko, vto, 1, tid);
    CP_COMMIT();

    float o[8][4];
    #pragma unroll
    for (int nt = 0; nt < 8; nt++)
        #pragma unroll
        for (int i = 0; i < 4; i++) o[nt][i] = 0.f;
    float m0 = -1e30f, m1 = -1e30f, l0 = 0.f, l1 = 0.f;

    for (int kt = 0; kt < ntiles; kt++) {
        if (kt + 1 < ntiles) CP_WAIT1(); else CP_WAIT0();
        __syncthreads();
        uint32_t stg = sb + (uint32_t)(kt & 1) * ABUF;

        float c[8][4];
        #pragma unroll
        for (int nt = 0; nt < 8; nt++)
            #pragma unroll
            for (int i = 0; i < 4; i++) c[nt][i] = 0.f;

        #pragma unroll
        for (int kc = 0; kc < 4; kc++) {
            uint32_t koff = (uint32_t)(kc * 16) * 2;
            uint32_t bfr[8][2];
            #pragma unroll
            for (int np = 0; np < 4; np++) {
                uint32_t r4[4];
                ldmx4(r4, stg + 0*TILEB + ((uint32_t)(np*16) + b_row) * TROWB + koff + b_kc*2);
                bfr[2*np][0] = r4[0]; bfr[2*np][1] = r4[1];
                bfr[2*np+1][0] = r4[2]; bfr[2*np+1][1] = r4[3];
            }
            #pragma unroll
            for (int nt = 0; nt < 8; nt++) mma16816(c[nt], qfh[kc], bfr[nt]);
            #pragma unroll
            for (int nt = 0; nt < 8; nt++) mma16816(c[nt], qfl[kc], bfr[nt]);
            #pragma unroll
            for (int np = 0; np < 4; np++) {
                uint32_t r4[4];
                ldmx4(r4, stg + 1*TILEB + ((uint32_t)(np*16) + b_row) * TROWB + koff + b_kc*2);
                bfr[2*np][0] = r4[0]; bfr[2*np][1] = r4[1];
                bfr[2*np+1][0] = r4[2]; bfr[2*np+1][1] = r4[3];
            }
            #pragma unroll
            for (int nt = 0; nt < 8; nt++) mma16816(c[nt], qfh[kc], bfr[nt]);
        }

        if (kt >= 2*qt) {
            int kb0 = kt * 64;
            int row0 = qbase + wid*16 + (lane >> 2);
            #pragma unroll
            for (int nt = 0; nt < 8; nt++) {
                int col = kb0 + nt*8 + (lane & 3)*2;
                if (col     > row0)     c[nt][0] = -1e30f;
                if (col + 1 > row0)     c[nt][1] = -1e30f;
                if (col     > row0 + 8) c[nt][2] = -1e30f;
                if (col + 1 > row0 + 8) c[nt][3] = -1e30f;
            }
        }

        float mx0 = -1e30f, mx1 = -1e30f;
        #pragma unroll
        for (int nt = 0; nt < 8; nt++) {
            mx0 = fmaxf(mx0, fmaxf(c[nt][0], c[nt][1]));
            mx1 = fmaxf(mx1, fmaxf(c[nt][2], c[nt][3]));
        }
        mx0 = fmaxf(mx0, __shfl_xor_sync(0xffffffffu, mx0, 1));
        mx0 = fmaxf(mx0, __shfl_xor_sync(0xffffffffu, mx0, 2));
        mx1 = fmaxf(mx1, __shfl_xor_sync(0xffffffffu, mx1, 1));
        mx1 = fmaxf(mx1, __shfl_xor_sync(0xffffffffu, mx1, 2));
        float nm0 = fmaxf(m0, mx0), nm1 = fmaxf(m1, mx1);
        float r0 = __expf(m0 - nm0), r1 = __expf(m1 - nm1);
        m0 = nm0; m1 = nm1;
        float s0 = 0.f, s1 = 0.f;
        #pragma unroll
        for (int nt = 0; nt < 8; nt++) {
            c[nt][0] = __expf(c[nt][0] - nm0);
            c[nt][1] = __expf(c[nt][1] - nm0);
            c[nt][2] = __expf(c[nt][2] - nm1);
            c[nt][3] = __expf(c[nt][3] - nm1);
            s0 += c[nt][0] + c[nt][1];
            s1 += c[nt][2] + c[nt][3];
        }
        s0 += __shfl_xor_sync(0xffffffffu, s0, 1);
        s0 += __shfl_xor_sync(0xffffffffu, s0, 2);
        s1 += __shfl_xor_sync(0xffffffffu, s1, 1);
        s1 += __shfl_xor_sync(0xffffffffu, s1, 2);
        l0 = l0 * r0 + s0;
        l1 = l1 * r1 + s1;
        #pragma unroll
        for (int nt = 0; nt < 8; nt++) {
            o[nt][0] *= r0; o[nt][1] *= r0;
            o[nt][2] *= r1; o[nt][3] *= r1;
        }

        uint32_t ph[4][4], pl[4][4];
        #pragma unroll
        for (int kc = 0; kc < 4; kc++) {
            float* e0 = c[2*kc];
            float* e1 = c[2*kc+1];
            ph[kc][0] = pack_bf2(e0[0], e0[1]);
            ph[kc][1] = pack_bf2(e0[2], e0[3]);
            ph[kc][2] = pack_bf2(e1[0], e1[1]);
            ph[kc][3] = pack_bf2(e1[2], e1[3]);
            pl[kc][0] = pack_bf2(bf_res(e0[0]), bf_res(e0[1]));
            pl[kc][1] = pack_bf2(bf_res(e0[2]), bf_res(e0[3]));
            pl[kc][2] = pack_bf2(bf_res(e1[0]), bf_res(e1[1]));
            pl[kc][3] = pack_bf2(bf_res(e1[2]), bf_res(e1[3]));
        }

        #pragma unroll
        for (int kc = 0; kc < 4; kc++) {
            uint32_t koff = (uint32_t)(kc * 16) * 2;
            uint32_t bfr[8][2];
            #pragma unroll
            for (int np = 0; np < 4; np++) {
                uint32_t r4[4];
                ldmx4(r4, stg + 2*TILEB + ((uint32_t)(np*16) + b_row) * TROWB + koff + b_kc*2);
                bfr[2*np][0] = r4[0]; bfr[2*np][1] = r4[1];
                bfr[2*np+1][0] = r4[2]; bfr[2*np+1][1] = r4[3];
            }
            #pragma unroll
            for (int nt = 0; nt < 8; nt++) mma16816(o[nt], ph[kc], bfr[nt]);
            #pragma unroll
            for (int nt = 0; nt < 8; nt++) mma16816(o[nt], pl[kc], bfr[nt]);
            #pragma unroll
            for (int np = 0; np < 4; np++) {
                uint32_t r4[4];
                ldmx4(r4, stg + 3*TILEB + ((uint32_t)(np*16) + b_row) * TROWB + koff + b_kc*2);
                bfr[2*np][0] = r4[0]; bfr[2*np][1] = r4[1];
                bfr[2*np+1][0] = r4[2]; bfr[2*np+1][1] = r4[3];
            }
            #pragma unroll
            for (int nt = 0; nt < 8; nt++) mma16816(o[nt], ph[kc], bfr[nt]);
        }

        __syncthreads();
        if (kt + 2 < ntiles) {
            load_kv(stg, Kh, Kl, VTh, VTl, qko, vto, kt + 2, tid);
            CP_COMMIT();
        }
    }

    float inv0 = 1.0f / l0, inv1 = 1.0f / l1;
    int row0 = qbase + wid*16 + (lane >> 2);
    int col0 = h*64 + (lane & 3)*2;
    size_t i0 = (((size_t)(b*S_ + row0))*D_ + col0) >> 1;
    size_t i1 = (((size_t)(b*S_ + row0 + 8))*D_ + col0) >> 1;
    uint32_t* OH = (uint32_t*)Oh;
    uint32_t* OL = (uint32_t*)Ol;
    #pragma unroll
    for (int nt = 0; nt < 8; nt++) {
        float a0 = o[nt][0]*inv0, a1 = o[nt][1]*inv0;
        float a2 = o[nt][2]*inv1, a3 = o[nt][3]*inv1;
        float h0 = bf_hi(a0), h1 = bf_hi(a1), h2 = bf_hi(a2), h3 = bf_hi(a3);
        OH[i0 + nt*4] = pack_bf2(h0, h1);
        OL[i0 + nt*4] = pack_bf2(a0 - h0, a1 - h1);
        OH[i1 + nt*4] = pack_bf2(h2, h3);
        OL[i1 + nt*4] = pack_bf2(a2 - h2, a3 - h3);
    }
}

// ---------------------------------------------------------------------------
extern "C" void kernel_launch(void* const* d_in, const int* in_sizes, int n_in,
                              void* d_out, int out_size)
{
    const float* x  = (const float*)d_in[0];
    const float* wq = (const float*)d_in[1];
    const float* wk = (const float*)d_in[2];
    const float* wv = (const float*)d_in[3];
    const float* wo = (const float*)d_in[4];
    const float* bo = (const float*)d_in[5];
    float* out = (float*)d_out;

    __nv_bfloat16 *xh, *xl, *wh, *wl, *qh2, *ql2, *kh2, *kl2, *vth, *vtl;
    cudaGetSymbolAddress((void**)&xh,  g_xh);
    cudaGetSymbolAddress((void**)&xl,  g_xl);
    cudaGetSymbolAddress((void**)&wh,  g_wh);
    cudaGetSymbolAddress((void**)&wl,  g_wl);
    cudaGetSymbolAddress((void**)&qh2, g_qh2);
    cudaGetSymbolAddress((void**)&ql2, g_ql2);
    cudaGetSymbolAddress((void**)&kh2, g_kh2);
    cudaGetSymbolAddress((void**)&kl2, g_kl2);
    cudaGetSymbolAddress((void**)&vth, g_vth);
    cudaGetSymbolAddress((void**)&vtl, g_vtl);

    cudaFuncSetAttribute(gemm_qkv, cudaFuncAttributeMaxDynamicSharedMemorySize, GSMEM);
    cudaFuncSetAttribute(gemm_out, cudaFuncAttributeMaxDynamicSharedMemorySize, GSMEM);
    cudaFuncSetAttribute(attn_hmma, cudaFuncAttributeMaxDynamicSharedMemorySize, ATT_SMEM);

    // one fused split for x + all 4 weights
    split_all<<<(XF4 + 4*WF4 + 255)/256, 256>>>(x, wq, wk, wv, wo, xh, xl, wh, wl);

    // fused Q/K/V projection (z selects weight + epilogue; V written transposed)
    dim3 gq(D_/128, M_/128, 3);   // (8, 32, 3)
    gemm_qkv<<<gq, 256, GSMEM>>>(xh, xl, wh, wl, qh2, ql2, kh2, kl2, vth, vtl);

    dim3 ga(S_/128, H_, B_);   // (16, 16, 2)
    attn_hmma<<<ga, 256, ATT_SMEM>>>(qh2, ql2, kh2, kl2, vth, vtl, xh, xl);

    dim3 gg(D_/128, M_/128);   // (8, 32)
    gemm_out<<<gg, 256, GSMEM>>>(xh, xl, wh + 3*NW, wl + 3*NW, bo, out);
}

// round 11
// speedup vs baseline: 1.5290x; 1.5290x over previous
#include <cuda_runtime.h>
#include <cuda_bf16.h>
#include <cstdint>

#define B_  2
#define S_  2048
#define D_  1024
#define H_  16
#define HD_ 64
#define M_  (B_*S_)   // 4096 rows
#define NW  (D_*D_)

// fp32 scratch (V)
__device__ float g_v[M_*D_];
// bf16 split scratch
__device__ __nv_bfloat16 g_xh[M_*D_];
__device__ __nv_bfloat16 g_xl[M_*D_];
__device__ __nv_bfloat16 g_wh[4][D_*D_];
__device__ __nv_bfloat16 g_wl[4][D_*D_];
// attention operands (head-major)
__device__ __nv_bfloat16 g_qh2[M_*D_];
__device__ __nv_bfloat16 g_ql2[M_*D_];
__device__ __nv_bfloat16 g_kh2[M_*D_];
__device__ __nv_bfloat16 g_kl2[M_*D_];
__device__ __nv_bfloat16 g_vth[M_*D_];
__device__ __nv_bfloat16 g_vtl[M_*D_];

// ---------------------------------------------------------------------------
// base-ISA PTX helpers (compute_103 generic: no tcgen05 available)
// ---------------------------------------------------------------------------
__device__ __forceinline__ uint32_t smem_to_u32(const void* p) {
    uint32_t a;
    asm("{ .reg .u64 tmp; cvta.to.shared.u64 tmp, %1; cvt.u32.u64 %0, tmp; }"
        : "=r"(a) : "l"(p));
    return a;
}
#define CP_ASYNC16(dst, src) \
    asm volatile("cp.async.cg.shared.global [%0], [%1], 16;" :: "r"(dst), "l"(src))
#define CP_COMMIT() asm volatile("cp.async.commit_group;" ::: "memory")
#define CP_WAIT0()  asm volatile("cp.async.wait_group 0;" ::: "memory")
#define CP_WAIT1()  asm volatile("cp.async.wait_group 1;" ::: "memory")

__device__ __forceinline__ void ldmx4(uint32_t* r, uint32_t addr) {
    asm volatile("ldmatrix.sync.aligned.m8n8.x4.shared.b16 {%0,%1,%2,%3}, [%4];"
        : "=r"(r[0]), "=r"(r[1]), "=r"(r[2]), "=r"(r[3]) : "r"(addr));
}
__device__ __forceinline__ void mma16816(float* c, const uint32_t* a, const uint32_t* b) {
    asm volatile("mma.sync.aligned.m16n8k16.row.col.f32.bf16.bf16.f32 "
        "{%0,%1,%2,%3}, {%4,%5,%6,%7}, {%8,%9}, {%0,%1,%2,%3};"
        : "+f"(c[0]), "+f"(c[1]), "+f"(c[2]), "+f"(c[3])
        : "r"(a[0]), "r"(a[1]), "r"(a[2]), "r"(a[3]), "r"(b[0]), "r"(b[1]));
}
__device__ __forceinline__ uint32_t pack_bf2(float a, float b) {   // low=a, high=b
    uint32_t r;
    asm("cvt.rn.bf16x2.f32 %0, %1, %2;" : "=r"(r) : "f"(b), "f"(a));
    return r;
}
__device__ __forceinline__ float bf_hi(float x) {
    return __bfloat162float(__float2bfloat16_rn(x));
}
__device__ __forceinline__ float bf_res(float x) { return x - bf_hi(x); }

// ---------------------------------------------------------------------------
// split_all: one launch splits x (1M float4) + 4 weights (256K float4 each)
// ---------------------------------------------------------------------------
#define XF4 (M_*D_/4)      // 1048576
#define WF4 (NW/4)         // 262144
__global__ __launch_bounds__(256) void split_all(
    const float* __restrict__ x,  const float* __restrict__ wq,
    const float* __restrict__ wk, const float* __restrict__ wv,
    const float* __restrict__ wo,
    __nv_bfloat16* __restrict__ xh, __nv_bfloat16* __restrict__ xl,
    __nv_bfloat16* __restrict__ wh, __nv_bfloat16* __restrict__ wl)
{
    int i = blockIdx.x * blockDim.x + threadIdx.x;
    const float* src;
    uint32_t *hi, *lo;
    int off;
    if (i < XF4) {
        src = x; hi = (uint32_t*)xh; lo = (uint32_t*)xl; off = i;
    } else {
        int j = i - XF4;
        int w = j >> 18;            // WF4 = 2^18
        off = j & (WF4 - 1);
        src = (w == 0) ? wq : (w == 1) ? wk : (w == 2) ? wv : wo;
        hi  = (uint32_t*)(wh + (size_t)w * NW);
        lo  = (uint32_t*)(wl + (size_t)w * NW);
    }
    float4 v = ((const float4*)src)[off];
    float hx = bf_hi(v.x), hy = bf_hi(v.y), hz = bf_hi(v.z), hw = bf_hi(v.w);
    hi[off*2]   = pack_bf2(hx, hy);
    hi[off*2+1] = pack_bf2(hz, hw);
    lo[off*2]   = pack_bf2(v.x - hx, v.y - hy);
    lo[off*2+1] = pack_bf2(v.z - hz, v.w - hw);
}

// ---------------------------------------------------------------------------
// v_transpose: fp32 [b,s,D] -> bf16 hi/lo transposed [b,h,64,s]
// ---------------------------------------------------------------------------
__global__ __launch_bounds__(256) void v_transpose(
    const float* __restrict__ src, __nv_bfloat16* __restrict__ hi,
    __nv_bfloat16* __restrict__ lo)
{
    __shared__ float t[128][65];
    int s0 = blockIdx.x * 128, h = blockIdx.y, b = blockIdx.z;
    int tid = threadIdx.x;
    {
        int sl = tid >> 1, ds = (tid & 1) * 32;
        const float* sp = src + ((size_t)(b*S_ + s0 + sl))*D_ + h*64 + ds;
        #pragma unroll
        for (int i = 0; i < 8; i++) {
            float4 v = *(const float4*)(sp + i*4);
            t[sl][ds+i*4+0] = v.x; t[sl][ds+i*4+1] = v.y;
            t[sl][ds+i*4+2] = v.z; t[sl][ds+i*4+3] = v.w;
        }
    }
    __syncthreads();
    int d = tid >> 2, ss = (tid & 3) * 32;
    uint32_t hp[16], lp[16];
    #pragma unroll
    for (int j = 0; j < 16; j++) {
        float x = t[ss+2*j][d], y = t[ss+2*j+1][d];
        float hx = bf_hi(x), hy = bf_hi(y);
        hp[j] = pack_bf2(hx, hy);
        lp[j] = pack_bf2(x - hx, y - hy);
    }
    size_t ob = ((size_t)((b*H_ + h)*64 + d))*S_ + s0 + ss;
    #pragma unroll
    for (int j = 0; j < 4; j++) {
        ((uint4*)(hi + ob))[j] = make_uint4(hp[4*j], hp[4*j+1], hp[4*j+2], hp[4*j+3]);
        ((uint4*)(lo + ob))[j] = make_uint4(lp[4*j], lp[4*j+1], lp[4*j+2], lp[4*j+3]);
    }
}

// ---------------------------------------------------------------------------
// HMMA GEMM core (validated): C = Ah*Bh^T + Ah*Bl^T + Al*Bh^T into c[2][8][4]
// ---------------------------------------------------------------------------
#define BK    32
#define ASTR  40
#define BUFB  (128*ASTR*2)
#define STAGEB (4*BUFB)
#define GSMEM (2*STAGEB)

__device__ __forceinline__ void stage_load(
    uint32_t sbase,
    const __nv_bfloat16* __restrict__ Ah, const __nv_bfloat16* __restrict__ Al,
    const __nv_bfloat16* __restrict__ Bh, const __nv_bfloat16* __restrict__ Bl,
    int m0, int n0, int kc, int tid)
{
    int r  = tid >> 1;
    int ch = (tid & 1) * 16;
    uint32_t so = (uint32_t)(r * (ASTR*2) + ch * 2);
    size_t ga = (size_t)(m0 + r) * D_ + kc + ch;
    size_t gb = (size_t)(n0 + r) * D_ + kc + ch;
    CP_ASYNC16(sbase + 0*BUFB + so,      Ah + ga);
    CP_ASYNC16(sbase + 0*BUFB + so + 16, Ah + ga + 8);
    CP_ASYNC16(sbase + 1*BUFB + so,      Al + ga);
    CP_ASYNC16(sbase + 1*BUFB + so + 16, Al + ga + 8);
    CP_ASYNC16(sbase + 2*BUFB + so,      Bh + gb);
    CP_ASYNC16(sbase + 2*BUFB + so + 16, Bh + gb + 8);
    CP_ASYNC16(sbase + 3*BUFB + so,      Bl + gb);
    CP_ASYNC16(sbase + 3*BUFB + so + 16, Bl + gb + 8);
}

#define GEMM_MAINLOOP(AhP, AlP, BhP, BlP)                                        \
    int wm = (wid >> 1) * 32;                                                    \
    int wn = (wid & 1) * 64;                                                     \
    int qq = lane >> 3, lr = lane & 7;                                           \
    uint32_t a_row = (uint32_t)((qq & 1) * 8 + lr);                              \
    uint32_t a_kc  = (uint32_t)((qq >> 1) * 8);                                  \
    uint32_t b_row = (uint32_t)((qq >> 1) * 8 + lr);                             \
    uint32_t b_kc  = (uint32_t)((qq & 1) * 8);                                   \
    float c[2][8][4];                                                            \
    _Pragma("unroll")                                                            \
    for (int mt = 0; mt < 2; mt++)                                               \
        _Pragma("unroll")                                                        \
        for (int nt = 0; nt < 8; nt++)                                           \
            _Pragma("unroll")                                                    \
            for (int i = 0; i < 4; i++) c[mt][nt][i] = 0.f;                      \
    stage_load(sb,          AhP, AlP, BhP, BlP, m0, n0, 0,  tid); CP_COMMIT();   \
    stage_load(sb + STAGEB, AhP, AlP, BhP, BlP, m0, n0, BK, tid); CP_COMMIT();   \
    const int NCH = D_ / BK;                                                     \
    for (int cc = 0; cc < NCH; cc++) {                                           \
        uint32_t stage = sb + (uint32_t)(cc & 1) * STAGEB;                       \
        CP_WAIT1();                                                              \
        __syncthreads();                                                         \
        uint32_t sAh = stage + 0*BUFB, sAl = stage + 1*BUFB;                     \
        uint32_t sBh = stage + 2*BUFB, sBl = stage + 3*BUFB;                     \
        _Pragma("unroll")                                                        \
        for (int ks = 0; ks < 2; ks++) {                                         \
            uint32_t koff = (uint32_t)(ks * 16) * 2;                             \
            uint32_t ah[2][4], al[2][4], bfr[8][2];                              \
            _Pragma("unroll")                                                    \
            for (int mt = 0; mt < 2; mt++)                                       \
                ldmx4(ah[mt], sAh + ((uint32_t)(wm + mt*16) + a_row) * (ASTR*2) + koff + a_kc*2); \
            _Pragma("unroll")                                                    \
            for (int mt = 0; mt < 2; mt++)                                       \
                ldmx4(al[mt], sAl + ((uint32_t)(wm + mt*16) + a_row) * (ASTR*2) + koff + a_kc*2); \
            _Pragma("unroll")                                                    \
            for (int np = 0; np < 4; np++) {                                     \
                uint32_t r4[4];                                                  \
                ldmx4(r4, sBh + ((uint32_t)(wn + np*16) + b_row) * (ASTR*2) + koff + b_kc*2); \
                bfr[2*np][0] = r4[0]; bfr[2*np][1] = r4[1];                      \
                bfr[2*np+1][0] = r4[2]; bfr[2*np+1][1] = r4[3];                  \
            }                                                                    \
            _Pragma("unroll")                                                    \
            for (int mt = 0; mt < 2; mt++)                                       \
                _Pragma("unroll")                                                \
                for (int nt = 0; nt < 8; nt++)                                   \
                    mma16816(c[mt][nt], ah[mt], bfr[nt]);                        \
            _Pragma("unroll")                                                    \
            for (int mt = 0; mt < 2; mt++)                                       \
                _Pragma("unroll")                                                \
                for (int nt = 0; nt < 8; nt++)                                   \
                    mma16816(c[mt][nt], al[mt], bfr[nt]);                        \
            _Pragma("unroll")                                                    \
            for (int np = 0; np < 4; np++) {                                     \
                uint32_t r4[4];                                                  \
                ldmx4(r4, sBl + ((uint32_t)(wn + np*16) + b_row) * (ASTR*2) + koff + b_kc*2); \
                bfr[2*np][0] = r4[0]; bfr[2*np][1] = r4[1];                      \
                bfr[2*np+1][0] = r4[2]; bfr[2*np+1][1] = r4[3];                  \
            }                                                                    \
            _Pragma("unroll")                                                    \
            for (int mt = 0; mt < 2; mt++)                                       \
                _Pragma("unroll")                                                \
                for (int nt = 0; nt < 8; nt++)                                   \
                    mma16816(c[mt][nt], ah[mt], bfr[nt]);                        \
        }                                                                        \
        __syncthreads();                                                         \
        if (cc + 2 < NCH)                                                        \
            stage_load(stage, AhP, AlP, BhP, BlP, m0, n0, (cc + 2) * BK, tid);   \
        CP_COMMIT();                                                             \
    }

// ---------------------------------------------------------------------------
// fused QKV projection: z=0 -> Q split head-major (scale 1/8),
//                       z=1 -> K split head-major, z=2 -> V fp32 [b,s,D]
// __launch_bounds__(256,2) pins regs <=128 so occupancy never drops to 1 CTA.
// ---------------------------------------------------------------------------
__global__ __launch_bounds__(256,2) void gemm_qkv(
    const __nv_bfloat16* __restrict__ Xh, const __nv_bfloat16* __restrict__ Xl,
    const __nv_bfloat16* __restrict__ Wh, const __nv_bfloat16* __restrict__ Wl,
    __nv_bfloat16* __restrict__ Qh, __nv_bfloat16* __restrict__ Ql,
    __nv_bfloat16* __restrict__ Kh, __nv_bfloat16* __restrict__ Kl,
    float* __restrict__ Vf)
{
    extern __shared__ char smem[];
    uint32_t sb = smem_to_u32(smem);
    int tid = threadIdx.x, wid = tid >> 5, lane = tid & 31;
    int n0 = blockIdx.x * 128;
    int m0 = blockIdx.y * 128;
    int z  = blockIdx.z;
    const __nv_bfloat16* Bh = Wh + (size_t)z * NW;
    const __nv_bfloat16* Bl = Wl + (size_t)z * NW;

    GEMM_MAINLOOP(Xh, Xl, Bh, Bl)

    int crow = lane >> 2, ccol = (lane & 3) * 2;
    if (z == 2) {
        #pragma unroll
        for (int mt = 0; mt < 2; mt++)
            #pragma unroll
            for (int nt = 0; nt < 8; nt++) {
                int m = m0 + wm + mt*16 + crow;
                int n = n0 + wn + nt*8 + ccol;
                *(float2*)(Vf + (size_t)m * D_ + n)     = make_float2(c[mt][nt][0], c[mt][nt][1]);
                *(float2*)(Vf + (size_t)(m+8) * D_ + n) = make_float2(c[mt][nt][2], c[mt][nt][3]);
            }
    } else {
        float scale = (z == 0) ? 0.125f : 1.0f;
        uint32_t* Yh = (uint32_t*)((z == 0) ? Qh : Kh);
        uint32_t* Yl = (uint32_t*)((z == 0) ? Ql : Kl);
        #pragma unroll
        for (int mt = 0; mt < 2; mt++)
            #pragma unroll
            for (int nt = 0; nt < 8; nt++) {
                int m = m0 + wm + mt*16 + crow;
                int n = n0 + wn + nt*8 + ccol;
                int b = m >> 11, s = m & (S_-1);
                int h = n >> 6,  d = n & 63;
                size_t i0 = (((size_t)(b*H_ + h) * S_ + s) * 64 + d) >> 1;
                size_t i1 = i0 + (8 * 64 >> 1);
                float x0 = c[mt][nt][0]*scale, x1 = c[mt][nt][1]*scale;
                float x2 = c[mt][nt][2]*scale, x3 = c[mt][nt][3]*scale;
                float h0 = bf_hi(x0), h1 = bf_hi(x1), h2 = bf_hi(x2), h3 = bf_hi(x3);
                Yh[i0] = pack_bf2(h0, h1);
                Yl[i0] = pack_bf2(x0 - h0, x1 - h1);
                Yh[i1] = pack_bf2(h2, h3);
                Yl[i1] = pack_bf2(x2 - h2, x3 - h3);
            }
    }
}

// ---------------------------------------------------------------------------
// output projection: A = ctx split, + bias, fp32 out
// ---------------------------------------------------------------------------
__global__ __launch_bounds__(256,2) void gemm_out(
    const __nv_bfloat16* __restrict__ Ch, const __nv_bfloat16* __restrict__ Cl,
    const __nv_bfloat16* __restrict__ Bh, const __nv_bfloat16* __restrict__ Bl,
    const float* __restrict__ bias, float* __restrict__ Y)
{
    extern __shared__ char smem[];
    uint32_t sb = smem_to_u32(smem);
    int tid = threadIdx.x, wid = tid >> 5, lane = tid & 31;
    int n0 = blockIdx.x * 128;
    int m0 = blockIdx.y * 128;

    GEMM_MAINLOOP(Ch, Cl, Bh, Bl)

    int crow = lane >> 2, ccol = (lane & 3) * 2;
    #pragma unroll
    for (int mt = 0; mt < 2; mt++)
        #pragma unroll
        for (int nt = 0; nt < 8; nt++) {
            int m = m0 + wm + mt*16 + crow;
            int n = n0 + wn + nt*8 + ccol;
            float b0 = bias[n], b1 = bias[n+1];
            *(float2*)(Y + (size_t)m * D_ + n)     = make_float2(c[mt][nt][0]+b0, c[mt][nt][1]+b1);
            *(float2*)(Y + (size_t)(m+8) * D_ + n) = make_float2(c[mt][nt][2]+b0, c[mt][nt][3]+b1);
        }
}

// ---------------------------------------------------------------------------
// HMMA flash attention (validated core, unchanged)
// ---------------------------------------------------------------------------
#define TSTR  72
#define TROWB (TSTR*2)
#define TILEB (64*TROWB)
#define ABUF  (4*TILEB)
#define ATT_SMEM (2*ABUF)
#define QHB   (128*TROWB)

__device__ __forceinline__ void load_kv(
    uint32_t dst,
    const __nv_bfloat16* __restrict__ Kh, const __nv_bfloat16* __restrict__ Kl,
    const __nv_bfloat16* __restrict__ VTh, const __nv_bfloat16* __restrict__ VTl,
    size_t qko, size_t vto, int kt, int tid)
{
    int r = tid >> 2, seg = (tid & 3) * 16;
    uint32_t off = (uint32_t)(r * TROWB + seg * 2);
    const __nv_bfloat16* kh = Kh  + qko + (size_t)(kt*64 + r)*64 + seg;
    const __nv_bfloat16* kl = Kl  + qko + (size_t)(kt*64 + r)*64 + seg;
    const __nv_bfloat16* vh = VTh + vto + (size_t)r*S_ + kt*64 + seg;
    const __nv_bfloat16* vl = VTl + vto + (size_t)r*S_ + kt*64 + seg;
    CP_ASYNC16(dst + 0*TILEB + off,      kh);  CP_ASYNC16(dst + 0*TILEB + off + 16, kh + 8);
    CP_ASYNC16(dst + 1*TILEB + off,      kl);  CP_ASYNC16(dst + 1*TILEB + off + 16, kl + 8);
    CP_ASYNC16(dst + 2*TILEB + off,      vh);  CP_ASYNC16(dst + 2*TILEB + off + 16, vh + 8);
    CP_ASYNC16(dst + 3*TILEB + off,      vl);  CP_ASYNC16(dst + 3*TILEB + off + 16, vl + 8);
}

__global__ __launch_bounds__(256,1) void attn_hmma(
    const __nv_bfloat16* __restrict__ Qh, const __nv_bfloat16* __restrict__ Ql,
    const __nv_bfloat16* __restrict__ Kh, const __nv_bfloat16* __restrict__ Kl,
    const __nv_bfloat16* __restrict__ VTh, const __nv_bfloat16* __restrict__ VTl,
    __nv_bfloat16* __restrict__ Oh, __nv_bfloat16* __restrict__ Ol)
{
    extern __shared__ char smem[];
    uint32_t sb = smem_to_u32(smem);
    int tid = threadIdx.x, wid = tid >> 5, lane = tid & 31;
    int qt = (int)(gridDim.x - 1u - blockIdx.x);
    int h  = blockIdx.y, b = blockIdx.z;
    int bh = b*H_ + h;
    int qbase = qt * 128;
    size_t qko = (size_t)bh * S_ * 64;
    size_t vto = (size_t)bh * 64 * S_;

    int qq = lane >> 3, lr = lane & 7;
    uint32_t a_row = (uint32_t)((qq & 1) * 8 + lr);
    uint32_t a_kc  = (uint32_t)((qq >> 1) * 8);
    uint32_t b_row = (uint32_t)((qq >> 1) * 8 + lr);
    uint32_t b_kc  = (uint32_t)((qq & 1) * 8);

    {
        int r = tid >> 1, dseg = (tid & 1) * 32;
        const __nv_bfloat16* qh = Qh + qko + (size_t)(qbase + r)*64 + dseg;
        const __nv_bfloat16* ql = Ql + qko + (size_t)(qbase + r)*64 + dseg;
        uint32_t dq = sb + ABUF + (uint32_t)(r * TROWB + dseg * 2);
        #pragma unroll
        for (int i = 0; i < 4; i++) {
            CP_ASYNC16(dq + i*16,       qh + i*8);
            CP_ASYNC16(dq + QHB + i*16, ql + i*8);
        }
        CP_COMMIT();
    }
    load_kv(sb, Kh, Kl, VTh, VTl, qko, vto, 0, tid);
    CP_COMMIT();

    uint32_t qfh[4][4], qfl[4][4];
    CP_WAIT1();
    __syncthreads();
    {
        uint32_t qb = sb + ABUF + ((uint32_t)(wid*16) + a_row) * TROWB + a_kc*2;
        #pragma unroll
        for (int kc = 0; kc < 4; kc++) {
            ldmx4(qfh[kc], qb + kc*32);
            ldmx4(qfl[kc], qb + QHB + kc*32);
        }
    }
    __syncthreads();
    int ntiles = 2*qt + 2;
    load_kv(sb + ABUF, Kh, Kl, VTh, VTl, qko, vto, 1, tid);
    CP_COMMIT();

    float o[8][4];
    #pragma unroll
    for (int nt = 0; nt < 8; nt++)
        #pragma unroll
        for (int i = 0; i < 4; i++) o[nt][i] = 0.f;
    float m0 = -1e30f, m1 = -1e30f, l0 = 0.f, l1 = 0.f;

    for (int kt = 0; kt < ntiles; kt++) {
        if (kt + 1 < ntiles) CP_WAIT1(); else CP_WAIT0();
        __syncthreads();
        uint32_t stg = sb + (uint32_t)(kt & 1) * ABUF;

        float c[8][4];
        #pragma unroll
        for (int nt = 0; nt < 8; nt++)
            #pragma unroll
            for (int i = 0; i < 4; i++) c[nt][i] = 0.f;

        #pragma unroll
        for (int kc = 0; kc < 4; kc++) {
            uint32_t koff = (uint32_t)(kc * 16) * 2;
            uint32_t bfr[8][2];
            #pragma unroll
            for (int np = 0; np < 4; np++) {
                uint32_t r4[4];
                ldmx4(r4, stg + 0*TILEB + ((uint32_t)(np*16) + b_row) * TROWB + koff + b_kc*2);
                bfr[2*np][0] = r4[0]; bfr[2*np][1] = r4[1];
                bfr[2*np+1][0] = r4[2]; bfr[2*np+1][1] = r4[3];
            }
            #pragma unroll
            for (int nt = 0; nt < 8; nt++) mma16816(c[nt], qfh[kc], bfr[nt]);
            #pragma unroll
            for (int nt = 0; nt < 8; nt++) mma16816(c[nt], qfl[kc], bfr[nt]);
            #pragma unroll
            for (int np = 0; np < 4; np++) {
                uint32_t r4[4];
                ldmx4(r4, stg + 1*TILEB + ((uint32_t)(np*16) + b_row) * TROWB + koff + b_kc*2);
                bfr[2*np][0] = r4[0]; bfr[2*np][1] = r4[1];
                bfr[2*np+1][0] = r4[2]; bfr[2*np+1][1] = r4[3];
            }
            #pragma unroll
            for (int nt = 0; nt < 8; nt++) mma16816(c[nt], qfh[kc], bfr[nt]);
        }

        if (kt >= 2*qt) {
            int kb0 = kt * 64;
            int row0 = qbase + wid*16 + (lane >> 2);
            #pragma unroll
            for (int nt = 0; nt < 8; nt++) {
                int col = kb0 + nt*8 + (lane & 3)*2;
                if (col     > row0)     c[nt][0] = -1e30f;
                if (col + 1 > row0)     c[nt][1] = -1e30f;
                if (col     > row0 + 8) c[nt][2] = -1e30f;
                if (col + 1 > row0 + 8) c[nt][3] = -1e30f;
            }
        }

        float mx0 = -1e30f, mx1 = -1e30f;
        #pragma unroll
        for (int nt = 0; nt < 8; nt++) {
            mx0 = fmaxf(mx0, fmaxf(c[nt][0], c[nt][1]));
            mx1 = fmaxf(mx1, fmaxf(c[nt][2], c[nt][3]));
        }
        mx0 = fmaxf(mx0, __shfl_xor_sync(0xffffffffu, mx0, 1));
        mx0 = fmaxf(mx0, __shfl_xor_sync(0xffffffffu, mx0, 2));
        mx1 = fmaxf(mx1, __shfl_xor_sync(0xffffffffu, mx1, 1));
        mx1 = fmaxf(mx1, __shfl_xor_sync(0xffffffffu, mx1, 2));
        float nm0 = fmaxf(m0, mx0), nm1 = fmaxf(m1, mx1);
        float r0 = __expf(m0 - nm0), r1 = __expf(m1 - nm1);
        m0 = nm0; m1 = nm1;
        float s0 = 0.f, s1 = 0.f;
        #pragma unroll
        for (int nt = 0; nt < 8; nt++) {
            c[nt][0] = __expf(c[nt][0] - nm0);
            c[nt][1] = __expf(c[nt][1] - nm0);
            c[nt][2] = __expf(c[nt][2] - nm1);
            c[nt][3] = __expf(c[nt][3] - nm1);
            s0 += c[nt][0] + c[nt][1];
            s1 += c[nt][2] + c[nt][3];
        }
        s0 += __shfl_xor_sync(0xffffffffu, s0, 1);
        s0 += __shfl_xor_sync(0xffffffffu, s0, 2);
        s1 += __shfl_xor_sync(0xffffffffu, s1, 1);
        s1 += __shfl_xor_sync(0xffffffffu, s1, 2);
        l0 = l0 * r0 + s0;
        l1 = l1 * r1 + s1;
        #pragma unroll
        for (int nt = 0; nt < 8; nt++) {
            o[nt][0] *= r0; o[nt][1] *= r0;
            o[nt][2] *= r1; o[nt][3] *= r1;
        }

        uint32_t ph[4][4], pl[4][4];
        #pragma unroll
        for (int kc = 0; kc < 4; kc++) {
            float* e0 = c[2*kc];
            float* e1 = c[2*kc+1];
            ph[kc][0] = pack_bf2(e0[0], e0[1]);
            ph[kc][1] = pack_bf2(e0[2], e0[3]);
            ph[kc][2] = pack_bf2(e1[0], e1[1]);
            ph[kc][3] = pack_bf2(e1[2], e1[3]);
            pl[kc][0] = pack_bf2(bf_res(e0[0]), bf_res(e0[1]));
            pl[kc][1] = pack_bf2(bf_res(e0[2]), bf_res(e0[3]));
            pl[kc][2] = pack_bf2(bf_res(e1[0]), bf_res(e1[1]));
            pl[kc][3] = pack_bf2(bf_res(e1[2]), bf_res(e1[3]));
        }

        #pragma unroll
        for (int kc = 0; kc < 4; kc++) {
            uint32_t koff = (uint32_t)(kc * 16) * 2;
            uint32_t bfr[8][2];
            #pragma unroll
            for (int np = 0; np < 4; np++) {
                uint32_t r4[4];
                ldmx4(r4, stg + 2*TILEB + ((uint32_t)(np*16) + b_row) * TROWB + koff + b_kc*2);
                bfr[2*np][0] = r4[0]; bfr[2*np][1] = r4[1];
                bfr[2*np+1][0] = r4[2]; bfr[2*np+1][1] = r4[3];
            }
            #pragma unroll
            for (int nt = 0; nt < 8; nt++) mma16816(o[nt], ph[kc], bfr[nt]);
            #pragma unroll
            for (int nt = 0; nt < 8; nt++) mma16816(o[nt], pl[kc], bfr[nt]);
            #pragma unroll
            for (int np = 0; np < 4; np++) {
                uint32_t r4[4];
                ldmx4(r4, stg + 3*TILEB + ((uint32_t)(np*16) + b_row) * TROWB + koff + b_kc*2);
                bfr[2*np][0] = r4[0]; bfr[2*np][1] = r4[1];
                bfr[2*np+1][0] = r4[2]; bfr[2*np+1][1] = r4[3];
            }
            #pragma unroll
            for (int nt = 0; nt < 8; nt++) mma16816(o[nt], ph[kc], bfr[nt]);
        }

        __syncthreads();
        if (kt + 2 < ntiles) {
            load_kv(stg, Kh, Kl, VTh, VTl, qko, vto, kt + 2, tid);
            CP_COMMIT();
        }
    }

    float inv0 = 1.0f / l0, inv1 = 1.0f / l1;
    int row0 = qbase + wid*16 + (lane >> 2);
    int col0 = h*64 + (lane & 3)*2;
    size_t i0 = (((size_t)(b*S_ + row0))*D_ + col0) >> 1;
    size_t i1 = (((size_t)(b*S_ + row0 + 8))*D_ + col0) >> 1;
    uint32_t* OH = (uint32_t*)Oh;
    uint32_t* OL = (uint32_t*)Ol;
    #pragma unroll
    for (int nt = 0; nt < 8; nt++) {
        float a0 = o[nt][0]*inv0, a1 = o[nt][1]*inv0;
        float a2 = o[nt][2]*inv1, a3 = o[nt][3]*inv1;
        float h0 = bf_hi(a0), h1 = bf_hi(a1), h2 = bf_hi(a2), h3 = bf_hi(a3);
        OH[i0 + nt*4] = pack_bf2(h0, h1);
        OL[i0 + nt*4] = pack_bf2(a0 - h0, a1 - h1);
        OH[i1 + nt*4] = pack_bf2(h2, h3);
        OL[i1 + nt*4] = pack_bf2(a2 - h2, a3 - h3);
    }
}

// ---------------------------------------------------------------------------
extern "C" void kernel_launch(void* const* d_in, const int* in_sizes, int n_in,
                              void* d_out, int out_size)
{
    const float* x  = (const float*)d_in[0];
    const float* wq = (const float*)d_in[1];
    const float* wk = (const float*)d_in[2];
    const float* wv = (const float*)d_in[3];
    const float* wo = (const float*)d_in[4];
    const float* bo = (const float*)d_in[5];
    float* out = (float*)d_out;

    float* vp;
    cudaGetSymbolAddress((void**)&vp, g_v);
    __nv_bfloat16 *xh, *xl, *wh, *wl, *qh2, *ql2, *kh2, *kl2, *vth, *vtl;
    cudaGetSymbolAddress((void**)&xh,  g_xh);
    cudaGetSymbolAddress((void**)&xl,  g_xl);
    cudaGetSymbolAddress((void**)&wh,  g_wh);
    cudaGetSymbolAddress((void**)&wl,  g_wl);
    cudaGetSymbolAddress((void**)&qh2, g_qh2);
    cudaGetSymbolAddress((void**)&ql2, g_ql2);
    cudaGetSymbolAddress((void**)&kh2, g_kh2);
    cudaGetSymbolAddress((void**)&kl2, g_kl2);
    cudaGetSymbolAddress((void**)&vth, g_vth);
    cudaGetSymbolAddress((void**)&vtl, g_vtl);

    cudaFuncSetAttribute(gemm_qkv, cudaFuncAttributeMaxDynamicSharedMemorySize, GSMEM);
    cudaFuncSetAttribute(gemm_out, cudaFuncAttributeMaxDynamicSharedMemorySize, GSMEM);
    cudaFuncSetAttribute(attn_hmma, cudaFuncAttributeMaxDynamicSharedMemorySize, ATT_SMEM);

    // one fused split for x + all 4 weights
    split_all<<<(XF4 + 4*WF4 + 255)/256, 256>>>(x, wq, wk, wv, wo, xh, xl, wh, wl);

    // fused Q/K/V projection (z selects weight + epilogue; V fp32)
    dim3 gq(D_/128, M_/128, 3);   // (8, 32, 3)
    gemm_qkv<<<gq, 256, GSMEM>>>(xh, xl, wh, wl, qh2, ql2, kh2, kl2, vp);

    v_transpose<<<dim3(S_/128, H_, B_), 256>>>(vp, vth, vtl);

    dim3 ga(S_/128, H_, B_);   // (16, 16, 2)
    attn_hmma<<<ga, 256, ATT_SMEM>>>(qh2, ql2, kh2, kl2, vth, vtl, xh, xl);

    dim3 gg(D_/128, M_/128);   // (8, 32)
    gemm_out<<<gg, 256, GSMEM>>>(xh, xl, wh + 3*NW, wl + 3*NW, bo, out);
}